// round 9
// baseline (speedup 1.0000x reference)
#include <cuda_runtime.h>
#include <cstdint>

// Problem dims
#define T_DIM 32
#define B_DIM 64
#define D_DIM 256
#define P_DIM 1024
#define M_TOT (T_DIM * B_DIM)   // 2048
#define KNOTS 17

// Scratch (static device globals — no runtime allocation)
__device__ float g_x[M_TOT * P_DIM];     // 8 MB: raw proj@A (tf32 product)
__device__ float g_inv[P_DIM];           // 1/||A_col||
__device__ float g_partial[512];
__device__ int   g_count = 0;

// RNA(f32 -> tf32) == truncate(bits + 0x1000); the MMA input converter
// truncates, so one IADD on the bits gives exact round-to-nearest-away.
#define RNA_BIAS 0x1000u

// ---------------------------------------------------------------------------
// Kernel 1: tf32 mma.sync GEMM.  C[2048,1024] = proj @ A  (raw, unnormalized).
// Fragment bits get +0x1000 (ALU pipe, hidden under HMMA) -> RNA rounding.
// Blocks with by==0 also accumulate column sum-of-squares of A from the B
// SMEM tiles and write g_inv — no separate norm kernel.
// ---------------------------------------------------------------------------
#define ASTRIDE 68
#define BSTRIDE 136
#define CHUNKA_F (128 * ASTRIDE)            // 8704 floats
#define CHUNKB_F (64 * BSTRIDE)             // 8704 floats
#define NORM_OFF (2 * CHUNKA_F + 2 * CHUNKB_F)          // 128 floats of partials
#define GEMM_SMEM ((NORM_OFF + 128) * 4)                // 139776 B

__device__ __forceinline__ void load_chunk(
    uint32_t sb, int buf, int kt, int m0, int n0,
    const float4* __restrict__ pa, const float4* __restrict__ pb, int tid)
{
    // A tile: 128 rows (m) x 16 float4 (k)
    #pragma unroll
    for (int t = 0; t < 8; ++t) {
        int idx = t * 256 + tid;
        int row = idx >> 4;                 // 0..127
        int c   = idx & 15;                 // 0..15
        uint32_t off = (uint32_t)((buf * CHUNKA_F + row * ASTRIDE + c * 4) * 4);
        const float4* s = pa + (size_t)(m0 + row) * (D_DIM / 4) + kt * 16 + c;
        asm volatile("cp.async.cg.shared.global [%0], [%1], 16;"
                     :: "r"(sb + off), "l"(s));
    }
    // B tile: 64 rows (k=d) x 32 float4 (n=p), native Amat layout
    #pragma unroll
    for (int t = 0; t < 8; ++t) {
        int idx = t * 256 + tid;
        int row = idx >> 5;                 // 0..63
        int c   = idx & 31;                 // 0..31
        uint32_t off = (uint32_t)((2 * CHUNKA_F + buf * CHUNKB_F
                                   + row * BSTRIDE + c * 4) * 4);
        const float4* s = pb + (size_t)(kt * 64 + row) * (P_DIM / 4) + n0 / 4 + c;
        asm volatile("cp.async.cg.shared.global [%0], [%1], 16;"
                     :: "r"(sb + off), "l"(s));
    }
}

__global__ __launch_bounds__(256, 1) void gemm_tc(
    const float* __restrict__ pA, const float* __restrict__ pB)
{
    extern __shared__ float sm[];
    uint32_t sb;
    asm("{ .reg .u64 t; cvta.to.shared.u64 t, %1; cvt.u32.u64 %0, t; }"
        : "=r"(sb) : "l"(sm));

    const int tid = threadIdx.x;
    const int wid = tid >> 5;
    const int lid = tid & 31;
    const int gid = lid >> 2;      // 0..7
    const int tig = lid & 3;       // 0..3
    const int wm  = (wid >> 2) * 64;
    const int wn  = (wid & 3) * 32;
    const int m0  = blockIdx.y * 128;
    const int n0  = blockIdx.x * 128;
    const bool do_norm = (blockIdx.y == 0);
    const int ncol = tid & 127;            // column for norm accumulation
    const int nhalf = tid >> 7;            // 0/1: k-range split

    const float4* pa = (const float4*)pA;
    const float4* pb = (const float4*)pB;

    float acc[4][4][4];
    #pragma unroll
    for (int mi = 0; mi < 4; ++mi)
        #pragma unroll
        for (int ni = 0; ni < 4; ++ni)
            #pragma unroll
            for (int r = 0; r < 4; ++r) acc[mi][ni][r] = 0.f;
    float nsq = 0.f;

    load_chunk(sb, 0, 0, m0, n0, pa, pb, tid);
    asm volatile("cp.async.commit_group;" ::: "memory");

    #pragma unroll
    for (int kt = 0; kt < 4; ++kt) {
        if (kt < 3) {
            load_chunk(sb, (kt + 1) & 1, kt + 1, m0, n0, pa, pb, tid);
            asm volatile("cp.async.commit_group;" ::: "memory");
            asm volatile("cp.async.wait_group 1;" ::: "memory");
        } else {
            asm volatile("cp.async.wait_group 0;" ::: "memory");
        }
        __syncthreads();

        const int buf = kt & 1;
        const float* As = sm + buf * CHUNKA_F;
        const float* Bs = sm + 2 * CHUNKA_F + buf * CHUNKB_F;

        if (do_norm) {
            const float* np = Bs + nhalf * 32 * BSTRIDE + ncol;
            #pragma unroll
            for (int j = 0; j < 32; ++j) {
                float v = np[j * BSTRIDE];
                nsq += v * v;
            }
        }

        #pragma unroll
        for (int ks = 0; ks < 8; ++ks) {
            const int kc = ks * 8;
            uint32_t a[4][4];
            #pragma unroll
            for (int mi = 0; mi < 4; ++mi) {
                const float* ap = As + (wm + mi * 16 + gid) * ASTRIDE + kc + tig;
                a[mi][0] = __float_as_uint(ap[0])               + RNA_BIAS;
                a[mi][1] = __float_as_uint(ap[8 * ASTRIDE])     + RNA_BIAS;
                a[mi][2] = __float_as_uint(ap[4])               + RNA_BIAS;
                a[mi][3] = __float_as_uint(ap[8 * ASTRIDE + 4]) + RNA_BIAS;
            }
            uint32_t b[4][2];
            #pragma unroll
            for (int ni = 0; ni < 4; ++ni) {
                const float* bp = Bs + (kc + tig) * BSTRIDE + wn + ni * 8 + gid;
                b[ni][0] = __float_as_uint(bp[0])               + RNA_BIAS;
                b[ni][1] = __float_as_uint(bp[4 * BSTRIDE])     + RNA_BIAS;
            }
            #pragma unroll
            for (int mi = 0; mi < 4; ++mi)
                #pragma unroll
                for (int ni = 0; ni < 4; ++ni)
                    asm volatile(
                        "mma.sync.aligned.m16n8k8.row.col.f32.tf32.tf32.f32 "
                        "{%0,%1,%2,%3}, {%4,%5,%6,%7}, {%8,%9}, {%0,%1,%2,%3};"
                        : "+f"(acc[mi][ni][0]), "+f"(acc[mi][ni][1]),
                          "+f"(acc[mi][ni][2]), "+f"(acc[mi][ni][3])
                        : "r"(a[mi][0]), "r"(a[mi][1]), "r"(a[mi][2]), "r"(a[mi][3]),
                          "r"(b[ni][0]), "r"(b[ni][1]));
        }
        __syncthreads();
    }

    // Norm epilogue (by==0 blocks): combine k-halves, write g_inv
    if (do_norm) {
        if (nhalf == 1) sm[NORM_OFF + ncol] = nsq;
        __syncthreads();
        if (nhalf == 0) {
            float t = nsq + sm[NORM_OFF + ncol];
            g_inv[n0 + ncol] = 1.f / fmaxf(sqrtf(t), 1e-12f);
        }
    }

    // C epilogue
    #pragma unroll
    for (int mi = 0; mi < 4; ++mi) {
        const int m = m0 + wm + mi * 16 + gid;
        #pragma unroll
        for (int ni = 0; ni < 4; ++ni) {
            const int n = n0 + wn + ni * 8 + tig * 2;
            float2 v0 = { acc[mi][ni][0], acc[mi][ni][1] };
            float2 v1 = { acc[mi][ni][2], acc[mi][ni][3] };
            *(float2*)&g_x[(size_t)m * P_DIM + n]       = v0;
            *(float2*)&g_x[(size_t)(m + 8) * P_DIM + n] = v1;
        }
    }
}

// ---------------------------------------------------------------------------
// Kernel 2: per (t,p) cos/sin means over b.  Parity-split Chebyshev:
//   cos((k+2)a) = 2cos(2a)cos(ka) - cos((k-2)a)
// Each thread runs ONE 8-step chain (even knots 2..16 or odd knots 1..15)
// for a 16-b quarter: serial depth halved, thread count doubled (262K).
// sub = tid>>6: par = sub&1 (knot parity), bq = sub>>1 (b quarter).
// Quarters merged via SMEM (24 KB); fused deterministic final reduction.
// ---------------------------------------------------------------------------
__global__ __launch_bounds__(512) void trig_kernel(float* __restrict__ out)
{
    const int t   = blockIdx.y;
    const int pl  = threadIdx.x & 63;
    const int sub = threadIdx.x >> 6;     // 0..7
    const int par = sub & 1;              // 0: odd knots, 1: even knots
    const int bq  = sub >> 1;             // 0..3: b quarter
    const int p   = blockIdx.x * 64 + pl;
    const float dt = 3.0f / 16.0f;
    const float sc = dt * g_inv[p];

    float ca[8], sa[8];
    #pragma unroll
    for (int i = 0; i < 8; ++i) { ca[i] = 0.f; sa[i] = 0.f; }

    const float* xp = g_x + (size_t)(t * B_DIM + bq * 16) * P_DIM + p;
    #pragma unroll 4
    for (int b = 0; b < 16; ++b) {
        float x = xp[(size_t)b * P_DIM];
        float s1, c1;
        __sincosf(x * sc, &s1, &c1);
        float c2 = fmaf(2.f * c1, c1, -1.f);      // cos(2a)
        const float tc = 2.f * c2;
        float cc, ss, pc, ps;
        if (par == 0) {                           // odd: k = 1,3,...,15
            cc = c1; ss = s1; pc = c1; ps = -s1;  // prev = k = -1
        } else {                                  // even: k = 2,4,...,16
            float s2 = 2.f * s1 * c1;             // sin(2a)
            cc = c2; ss = s2; pc = 1.f; ps = 0.f; // prev = k = 0
        }
        #pragma unroll
        for (int i = 0; i < 8; ++i) {
            ca[i] += cc;
            sa[i] += ss;
            float nc = fmaf(tc, cc, -pc);
            float ns = fmaf(tc, ss, -ps);
            pc = cc; ps = ss; cc = nc; ss = ns;
        }
    }

    // Merge quarters 1..3 into quarter 0 (per parity; knots disjoint)
    __shared__ float mg[3][2][64][8][2];          // 24 KB
    if (bq > 0) {
        #pragma unroll
        for (int i = 0; i < 8; ++i) {
            mg[bq - 1][par][pl][i][0] = ca[i];
            mg[bq - 1][par][pl][i][1] = sa[i];
        }
    }
    __syncthreads();

    float val = 0.f;
    if (bq == 0) {
        const float invB = 1.f / (float)B_DIM;
        #pragma unroll
        for (int i = 0; i < 8; ++i) {
            int k = par ? (2 * i + 2) : (2 * i + 1);
            float C = ca[i] + mg[0][par][pl][i][0] + mg[1][par][pl][i][0]
                            + mg[2][par][pl][i][0];
            float S = sa[i] + mg[0][par][pl][i][1] + mg[1][par][pl][i][1]
                            + mg[2][par][pl][i][1];
            float tk   = (float)k * dt;
            float phik = expf(-0.5f * tk * tk);
            float wk   = ((k == 16) ? dt : 2.f * dt) * phik;
            float cm = C * invB - phik;
            float sm = S * invB;
            val += wk * (cm * cm + sm * sm);
        }
        val *= (float)B_DIM;
    }

    __shared__ float red[512];
    red[threadIdx.x] = val;
    __syncthreads();
    #pragma unroll
    for (int s = 256; s > 0; s >>= 1) {
        if (threadIdx.x < s) red[threadIdx.x] += red[threadIdx.x + s];
        __syncthreads();
    }

    __shared__ int is_last;
    if (threadIdx.x == 0) {
        g_partial[blockIdx.y * gridDim.x + blockIdx.x] = red[0];
        __threadfence();
        int prev = atomicAdd(&g_count, 1);
        is_last = (prev == (int)(gridDim.x * gridDim.y) - 1);
    }
    __syncthreads();

    if (is_last) {
        red[threadIdx.x] = g_partial[threadIdx.x];
        __syncthreads();
        #pragma unroll
        for (int s = 256; s > 0; s >>= 1) {
            if (threadIdx.x < s) red[threadIdx.x] += red[threadIdx.x + s];
            __syncthreads();
        }
        if (threadIdx.x == 0) {
            out[0] = red[0] * (1.0f / (float)(T_DIM * P_DIM));
            g_count = 0;   // reset so graph replays are deterministic
        }
    }
}

// ---------------------------------------------------------------------------
extern "C" void kernel_launch(void* const* d_in, const int* in_sizes, int n_in,
                              void* d_out, int out_size)
{
    const float* proj = (const float*)d_in[0];   // (32,64,256)
    const float* Amat = (const float*)d_in[1];   // (256,1024)
    float* out = (float*)d_out;

    cudaFuncSetAttribute(gemm_tc, cudaFuncAttributeMaxDynamicSharedMemorySize,
                         GEMM_SMEM);

    dim3 g1(P_DIM / 128, M_TOT / 128);   // (8, 16)
    gemm_tc<<<g1, 256, GEMM_SMEM>>>(proj, Amat);

    dim3 g2(P_DIM / 64, T_DIM);          // (16, 32) -> 512 blocks
    trig_kernel<<<g2, 512>>>(out);
}

// round 10
// speedup vs baseline: 1.1173x; 1.1173x over previous
#include <cuda_runtime.h>
#include <cstdint>

// Problem dims
#define T_DIM 32
#define B_DIM 64
#define D_DIM 256
#define P_DIM 1024
#define M_TOT (T_DIM * B_DIM)   // 2048
#define KNOTS 17

// Scratch (static device globals — no runtime allocation)
__device__ float g_x[M_TOT * P_DIM];     // 8 MB: raw proj@A (tf32 product)
__device__ float g_inv[P_DIM];           // 1/||A_col||
__device__ float g_partial[256];
__device__ int   g_count = 0;

// RNA(f32 -> tf32) == truncate(bits + 0x1000); the MMA input converter
// truncates, so one IADD on the bits gives exact round-to-nearest-away.
#define RNA_BIAS 0x1000u

// ---------------------------------------------------------------------------
// Kernel 1: tf32 mma.sync GEMM.  C[2048,1024] = proj @ A  (raw, unnormalized).
// Fragment bits get +0x1000 (ALU pipe, hidden under HMMA) -> RNA rounding.
// Blocks with by==0 also accumulate column sum-of-squares of A from the B
// SMEM tiles and write g_inv — no separate norm kernel.
// ---------------------------------------------------------------------------
#define ASTRIDE 68
#define BSTRIDE 136
#define CHUNKA_F (128 * ASTRIDE)            // 8704 floats
#define CHUNKB_F (64 * BSTRIDE)             // 8704 floats
#define NORM_OFF (2 * CHUNKA_F + 2 * CHUNKB_F)          // 128 floats of partials
#define GEMM_SMEM ((NORM_OFF + 128) * 4)                // 139776 B

__device__ __forceinline__ void load_chunk(
    uint32_t sb, int buf, int kt, int m0, int n0,
    const float4* __restrict__ pa, const float4* __restrict__ pb, int tid)
{
    // A tile: 128 rows (m) x 16 float4 (k)
    #pragma unroll
    for (int t = 0; t < 8; ++t) {
        int idx = t * 256 + tid;
        int row = idx >> 4;                 // 0..127
        int c   = idx & 15;                 // 0..15
        uint32_t off = (uint32_t)((buf * CHUNKA_F + row * ASTRIDE + c * 4) * 4);
        const float4* s = pa + (size_t)(m0 + row) * (D_DIM / 4) + kt * 16 + c;
        asm volatile("cp.async.cg.shared.global [%0], [%1], 16;"
                     :: "r"(sb + off), "l"(s));
    }
    // B tile: 64 rows (k=d) x 32 float4 (n=p), native Amat layout
    #pragma unroll
    for (int t = 0; t < 8; ++t) {
        int idx = t * 256 + tid;
        int row = idx >> 5;                 // 0..63
        int c   = idx & 31;                 // 0..31
        uint32_t off = (uint32_t)((2 * CHUNKA_F + buf * CHUNKB_F
                                   + row * BSTRIDE + c * 4) * 4);
        const float4* s = pb + (size_t)(kt * 64 + row) * (P_DIM / 4) + n0 / 4 + c;
        asm volatile("cp.async.cg.shared.global [%0], [%1], 16;"
                     :: "r"(sb + off), "l"(s));
    }
}

__global__ __launch_bounds__(256, 1) void gemm_tc(
    const float* __restrict__ pA, const float* __restrict__ pB)
{
    extern __shared__ float sm[];
    uint32_t sb;
    asm("{ .reg .u64 t; cvta.to.shared.u64 t, %1; cvt.u32.u64 %0, t; }"
        : "=r"(sb) : "l"(sm));

    const int tid = threadIdx.x;
    const int wid = tid >> 5;
    const int lid = tid & 31;
    const int gid = lid >> 2;      // 0..7
    const int tig = lid & 3;       // 0..3
    const int wm  = (wid >> 2) * 64;
    const int wn  = (wid & 3) * 32;
    const int m0  = blockIdx.y * 128;
    const int n0  = blockIdx.x * 128;
    const bool do_norm = (blockIdx.y == 0);
    const int ncol = tid & 127;            // column for norm accumulation
    const int nhalf = tid >> 7;            // 0/1: k-range split

    const float4* pa = (const float4*)pA;
    const float4* pb = (const float4*)pB;

    float acc[4][4][4];
    #pragma unroll
    for (int mi = 0; mi < 4; ++mi)
        #pragma unroll
        for (int ni = 0; ni < 4; ++ni)
            #pragma unroll
            for (int r = 0; r < 4; ++r) acc[mi][ni][r] = 0.f;
    float nsq = 0.f;

    load_chunk(sb, 0, 0, m0, n0, pa, pb, tid);
    asm volatile("cp.async.commit_group;" ::: "memory");

    #pragma unroll
    for (int kt = 0; kt < 4; ++kt) {
        if (kt < 3) {
            load_chunk(sb, (kt + 1) & 1, kt + 1, m0, n0, pa, pb, tid);
            asm volatile("cp.async.commit_group;" ::: "memory");
            asm volatile("cp.async.wait_group 1;" ::: "memory");
        } else {
            asm volatile("cp.async.wait_group 0;" ::: "memory");
        }
        __syncthreads();

        const int buf = kt & 1;
        const float* As = sm + buf * CHUNKA_F;
        const float* Bs = sm + 2 * CHUNKA_F + buf * CHUNKB_F;

        if (do_norm) {
            const float* np = Bs + nhalf * 32 * BSTRIDE + ncol;
            #pragma unroll
            for (int j = 0; j < 32; ++j) {
                float v = np[j * BSTRIDE];
                nsq += v * v;
            }
        }

        #pragma unroll
        for (int ks = 0; ks < 8; ++ks) {
            const int kc = ks * 8;
            uint32_t a[4][4];
            #pragma unroll
            for (int mi = 0; mi < 4; ++mi) {
                const float* ap = As + (wm + mi * 16 + gid) * ASTRIDE + kc + tig;
                a[mi][0] = __float_as_uint(ap[0])               + RNA_BIAS;
                a[mi][1] = __float_as_uint(ap[8 * ASTRIDE])     + RNA_BIAS;
                a[mi][2] = __float_as_uint(ap[4])               + RNA_BIAS;
                a[mi][3] = __float_as_uint(ap[8 * ASTRIDE + 4]) + RNA_BIAS;
            }
            uint32_t b[4][2];
            #pragma unroll
            for (int ni = 0; ni < 4; ++ni) {
                const float* bp = Bs + (kc + tig) * BSTRIDE + wn + ni * 8 + gid;
                b[ni][0] = __float_as_uint(bp[0])               + RNA_BIAS;
                b[ni][1] = __float_as_uint(bp[4 * BSTRIDE])     + RNA_BIAS;
            }
            #pragma unroll
            for (int mi = 0; mi < 4; ++mi)
                #pragma unroll
                for (int ni = 0; ni < 4; ++ni)
                    asm volatile(
                        "mma.sync.aligned.m16n8k8.row.col.f32.tf32.tf32.f32 "
                        "{%0,%1,%2,%3}, {%4,%5,%6,%7}, {%8,%9}, {%0,%1,%2,%3};"
                        : "+f"(acc[mi][ni][0]), "+f"(acc[mi][ni][1]),
                          "+f"(acc[mi][ni][2]), "+f"(acc[mi][ni][3])
                        : "r"(a[mi][0]), "r"(a[mi][1]), "r"(a[mi][2]), "r"(a[mi][3]),
                          "r"(b[ni][0]), "r"(b[ni][1]));
        }
        __syncthreads();
    }

    // Norm epilogue (by==0 blocks): combine k-halves, write g_inv
    if (do_norm) {
        if (nhalf == 1) sm[NORM_OFF + ncol] = nsq;
        __syncthreads();
        if (nhalf == 0) {
            float t = nsq + sm[NORM_OFF + ncol];
            g_inv[n0 + ncol] = 1.f / fmaxf(sqrtf(t), 1e-12f);
        }
    }

    // C epilogue
    #pragma unroll
    for (int mi = 0; mi < 4; ++mi) {
        const int m = m0 + wm + mi * 16 + gid;
        #pragma unroll
        for (int ni = 0; ni < 4; ++ni) {
            const int n = n0 + wn + ni * 8 + tig * 2;
            float2 v0 = { acc[mi][ni][0], acc[mi][ni][1] };
            float2 v1 = { acc[mi][ni][2], acc[mi][ni][3] };
            *(float2*)&g_x[(size_t)m * P_DIM + n]       = v0;
            *(float2*)&g_x[(size_t)(m + 8) * P_DIM + n] = v1;
        }
    }
}

// ---------------------------------------------------------------------------
// Kernel 2: per (t,p) cos/sin means over b.  R8 thread layout (4 b-quarters
// x 128 p = 512 threads), but the knot recurrence runs as TWO independent
// 8-step parity chains per thread (one sincos + one double-angle seed):
//   cos((k+2)a) = 2cos(2a)cos(ka) - cos((k-2)a)
// Same op count as the 16-step chain, half the serial RAW depth, ~4-way ILP.
// Quarter partial knot-sums merged via SMEM; fused deterministic reduction.
// ---------------------------------------------------------------------------
__global__ __launch_bounds__(512) void trig_kernel(float* __restrict__ out)
{
    const int t  = blockIdx.y;
    const int pl = threadIdx.x & 127;
    const int qt = threadIdx.x >> 7;        // 0..3: b-quarter
    const int p  = blockIdx.x * 128 + pl;
    const float dt = 3.0f / 16.0f;
    const float sc = dt * g_inv[p];

    // ca[2i] / sa[2i]   : odd knot  k = 2i+1
    // ca[2i+1] / sa[2i+1]: even knot k = 2i+2
    float ca[KNOTS - 1], sa[KNOTS - 1];
    #pragma unroll
    for (int k = 0; k < KNOTS - 1; ++k) { ca[k] = 0.f; sa[k] = 0.f; }

    const float* xp = g_x + (size_t)(t * B_DIM + qt * 16) * P_DIM + p;
    #pragma unroll 2
    for (int b = 0; b < 16; ++b) {
        float x = xp[(size_t)b * P_DIM];
        float s1, c1;
        __sincosf(x * sc, &s1, &c1);
        float c2 = fmaf(2.f * c1, c1, -1.f);      // cos(2a)
        float s2 = 2.f * s1 * c1;                 // sin(2a)
        const float tc = 2.f * c2;
        // odd chain: cur k=1, prev k=-1
        float oc = c1, os = s1, opc = c1, ops = -s1;
        // even chain: cur k=2, prev k=0
        float ec = c2, es = s2, epc = 1.f, eps = 0.f;
        #pragma unroll
        for (int i = 0; i < 8; ++i) {
            ca[2 * i]     += oc;  sa[2 * i]     += os;
            ca[2 * i + 1] += ec;  sa[2 * i + 1] += es;
            float noc = fmaf(tc, oc, -opc);
            float nos = fmaf(tc, os, -ops);
            float nec = fmaf(tc, ec, -epc);
            float nes = fmaf(tc, es, -eps);
            opc = oc; ops = os; oc = noc; os = nos;
            epc = ec; eps = es; ec = nec; es = nes;
        }
    }

    // Merge quarters 1..3 into quarter 0 via SMEM (48 KB)
    __shared__ float mc[3][KNOTS - 1][128];
    __shared__ float ms[3][KNOTS - 1][128];
    if (qt > 0) {
        #pragma unroll
        for (int k = 0; k < KNOTS - 1; ++k) {
            mc[qt - 1][k][pl] = ca[k];
            ms[qt - 1][k][pl] = sa[k];
        }
    }
    __syncthreads();

    float val = 0.f;
    if (qt == 0) {
        const float invB = 1.f / (float)B_DIM;
        #pragma unroll
        for (int k = 1; k <= 16; ++k) {
            float tk   = (float)k * dt;
            float phik = expf(-0.5f * tk * tk);
            float wk   = ((k == 16) ? dt : 2.f * dt) * phik;
            float cs = ca[k - 1] + mc[0][k - 1][pl] + mc[1][k - 1][pl]
                                 + mc[2][k - 1][pl];
            float ss = sa[k - 1] + ms[0][k - 1][pl] + ms[1][k - 1][pl]
                                 + ms[2][k - 1][pl];
            float cm = cs * invB - phik;
            float smn = ss * invB;
            val += wk * (cm * cm + smn * smn);
        }
        val *= (float)B_DIM;
    }

    __shared__ float red[512];
    red[threadIdx.x] = val;
    __syncthreads();
    #pragma unroll
    for (int s = 256; s > 0; s >>= 1) {
        if (threadIdx.x < s) red[threadIdx.x] += red[threadIdx.x + s];
        __syncthreads();
    }

    __shared__ int is_last;
    if (threadIdx.x == 0) {
        g_partial[blockIdx.y * gridDim.x + blockIdx.x] = red[0];
        __threadfence();
        int prev = atomicAdd(&g_count, 1);
        is_last = (prev == (int)(gridDim.x * gridDim.y) - 1);
    }
    __syncthreads();

    if (is_last) {
        float v = (threadIdx.x < 256) ? g_partial[threadIdx.x] : 0.f;
        red[threadIdx.x] = v;
        __syncthreads();
        #pragma unroll
        for (int s = 256; s > 0; s >>= 1) {
            if (threadIdx.x < s) red[threadIdx.x] += red[threadIdx.x + s];
            __syncthreads();
        }
        if (threadIdx.x == 0) {
            out[0] = red[0] * (1.0f / (float)(T_DIM * P_DIM));
            g_count = 0;   // reset so graph replays are deterministic
        }
    }
}

// ---------------------------------------------------------------------------
extern "C" void kernel_launch(void* const* d_in, const int* in_sizes, int n_in,
                              void* d_out, int out_size)
{
    const float* proj = (const float*)d_in[0];   // (32,64,256)
    const float* Amat = (const float*)d_in[1];   // (256,1024)
    float* out = (float*)d_out;

    cudaFuncSetAttribute(gemm_tc, cudaFuncAttributeMaxDynamicSharedMemorySize,
                         GEMM_SMEM);

    dim3 g1(P_DIM / 128, M_TOT / 128);   // (8, 16)
    gemm_tc<<<g1, 256, GEMM_SMEM>>>(proj, Amat);

    dim3 g2(P_DIM / 128, T_DIM);         // (8, 32) -> 256 blocks
    trig_kernel<<<g2, 512>>>(out);
}